// round 11
// baseline (speedup 1.0000x reference)
#include <cuda_runtime.h>
#include <cstdint>

#define FULLMASK 0xffffffffu
#define NMAX 100000

static __device__ float g_sum_i[NMAX];
static __device__ float g_sum_j[NMAX];
static __device__ float g_cnt_i[NMAX];
static __device__ float g_cnt_j[NMAX];

__device__ __forceinline__ uint32_t smem_u32(const void* p) {
    uint32_t a;
    asm("{ .reg .u64 t; cvta.to.shared.u64 t, %1; cvt.u32.u64 %0, t; }"
        : "=r"(a) : "l"(p));
    return a;
}
__device__ __forceinline__ uint32_t packh2(float lo, float hi) {
    uint32_t d;   // d.lo = f16(lo), d.hi = f16(hi)
    asm("cvt.rn.f16x2.f32 %0, %1, %2;" : "=r"(d) : "f"(hi), "f"(lo));
    return d;
}
__device__ __forceinline__ uint32_t h2add(uint32_t a, uint32_t b) {
    uint32_t d; asm("add.f16x2 %0, %1, %2;" : "=r"(d) : "r"(a), "r"(b)); return d;
}
__device__ __forceinline__ uint32_t h2mul(uint32_t a, uint32_t b) {
    uint32_t d; asm("mul.f16x2 %0, %1, %2;" : "=r"(d) : "r"(a), "r"(b)); return d;
}
__device__ __forceinline__ uint32_t h2fma(uint32_t a, uint32_t b, uint32_t c) {
    uint32_t d; asm("fma.rn.f16x2 %0, %1, %2, %3;" : "=r"(d) : "r"(a), "r"(b), "r"(c)); return d;
}
__device__ __forceinline__ uint32_t tanh2(uint32_t a) {
    uint32_t d; asm("tanh.approx.f16x2 %0, %1;" : "=r"(d) : "r"(a)); return d;
}
// silu on an f16x2 pair: zh=z/2; zh*tanh(zh)+zh  (1 MUFU per pair)
__device__ __forceinline__ uint32_t silu2(uint32_t z) {
    uint32_t zh = h2mul(z, 0x38003800u);   // (0.5, 0.5)
    return h2fma(zh, tanh2(zh), zh);
}
__device__ __forceinline__ void unpackh2(uint32_t v, float& a, float& b) {
    asm("{ .reg .f16 l, h; mov.b32 {l, h}, %2;"
        " cvt.f32.f16 %0, l; cvt.f32.f16 %1, h; }"
        : "=f"(a), "=f"(b) : "r"(v));
}
__device__ __forceinline__ void ldsm4(uint32_t* r, uint32_t addr) {
    asm volatile("ldmatrix.sync.aligned.m8n8.x4.shared.b16 {%0,%1,%2,%3}, [%4];"
                 : "=r"(r[0]), "=r"(r[1]), "=r"(r[2]), "=r"(r[3]) : "r"(addr));
}
__device__ __forceinline__ void mma_f16(float* d, const uint32_t* a,
                                        uint32_t b0, uint32_t b1) {
    asm volatile(
        "mma.sync.aligned.m16n8k16.row.col.f32.f16.f16.f32 "
        "{%0,%1,%2,%3}, {%4,%5,%6,%7}, {%8,%9}, {%0,%1,%2,%3};"
        : "+f"(d[0]), "+f"(d[1]), "+f"(d[2]), "+f"(d[3])
        : "r"(a[0]), "r"(a[1]), "r"(a[2]), "r"(a[3]), "r"(b0), "r"(b1));
}
__device__ __forceinline__ uint32_t swz(uint32_t off) {
    return off ^ ((off >> 3) & 0x70);   // SW128: bits[6:4] ^= bits[9:7]
}

__global__ void zero_kernel(int n) {
    int t = blockIdx.x * blockDim.x + threadIdx.x;
    if (t < n) {
        g_sum_i[t] = 0.f; g_sum_j[t] = 0.f;
        g_cnt_i[t] = 0.f; g_cnt_j[t] = 0.f;
    }
}
__global__ void dummy_kernel() {}
__global__ void finalize_kernel(float* __restrict__ out, int n) {
    int t = blockIdx.x * blockDim.x + threadIdx.x;
    if (t < n) {
        out[t] = g_sum_i[t] / fmaxf(g_cnt_i[t], 1.f)
               + g_sum_j[t] / fmaxf(g_cnt_j[t], 1.f);
    }
}

// CTA-cooperative: task = 128 edges = 256 rows. Layer-0 -> h1 f16 in SMEM
// (shared by all warps); 16 warps tile the 256x128x128 GEMM as m32 x n64 each.
__global__ void __launch_bounds__(512, 1)
edge_kernel(const float* __restrict__ v,
            const float* __restrict__ r_ij,
            const float* __restrict__ W0,
            const float* __restrict__ b0,
            const float* __restrict__ W1,
            const float* __restrict__ b1,
            const float* __restrict__ W2,
            const float* __restrict__ b2,
            const int* __restrict__ ei0,
            const int* __restrict__ ei1,
            int E) {
    extern __shared__ __align__(1024) unsigned char dyn[];
    // dyn: [0,32K) h1 cols 0-63 | [32K,64K) h1 cols 64-127 | [64K,96K) W1 B-blocks
    __shared__ float4 W0s4[128];
    __shared__ float2 s_b0[64];       // b0 pairs
    __shared__ uint32_t s_b1h[64];    // b1 pairs as f16x2
    __shared__ float2 s_w2[64];       // W2 pairs
    __shared__ float4 s_ed[2][128];   // (rr, dx, dy, dz) double-buffered
    __shared__ int2   s_ij[2][128];

    const int tid = threadIdx.x;
    const uint32_t h1b = smem_u32(dyn);
    uint2* Bp = (uint2*)(dyn + 65536);

    // ---- one-time init: W1 -> fragment-shaped B blocks + small weights ----
    // block[kk][ntp] (kk=0..7, ntp=0..15): 32 lanes x uint2; lane(m=l&3,q=l>>2):
    //   n = ntp*8+q, k0 = 16*kk+2*m: {h2(W1T[k0][n],W1T[k0+1][n]), h2(+8,+9)}
    for (int idx = tid; idx < 8 * 16 * 32; idx += 512) {
        int l = idx & 31, ntp = (idx >> 5) & 15, kk = idx >> 9;
        int n = ntp * 8 + (l >> 2);
        int k0 = 16 * kk + 2 * (l & 3);
        const float* wn = W1 + n * 128;
        Bp[idx] = make_uint2(packh2(wn[k0],     wn[k0 + 1]),
                             packh2(wn[k0 + 8], wn[k0 + 9]));
    }
    if (tid < 128) W0s4[tid] = ((const float4*)W0)[tid];
    if (tid < 64) {
        s_b0[tid]  = make_float2(b0[2 * tid], b0[2 * tid + 1]);
        s_b1h[tid] = packh2(b1[2 * tid], b1[2 * tid + 1]);
        s_w2[tid]  = make_float2(W2[2 * tid], W2[2 * tid + 1]);
    }

    const int lane = tid & 31;
    const int w    = tid >> 5;
    const int m    = lane & 3;
    const int q    = lane >> 2;
    const int mg   = w >> 1;          // m-group: rows mg*32 .. mg*32+31
    const int nh   = w & 1;           // n-half: cols nh*64 .. +63
    const float b2v = b2[0];
    const float sgnf = (lane & 1) ? -1.f : 1.f;   // h1 row parity = lane&1
    const int ntask = (E + 127) >> 7;

    // prologue gather for first task
    auto gather = [&](int task, int buf) {
        if (tid < 128 && task < ntask) {
            int e = (task << 7) + tid;
            bool valid = e < E;
            int ec = valid ? e : E - 1;
            int ii = ei0[ec], jj = ei1[ec];
            float a0 = r_ij[3 * ec], a1 = r_ij[3 * ec + 1], a2 = r_ij[3 * ec + 2];
            float rr = sqrtf(a0 * a0 + a1 * a1 + a2 * a2) * (1.0f / 3.0f);
            s_ed[buf][tid] = make_float4(rr,
                                         v[3 * ii]     - v[3 * jj],
                                         v[3 * ii + 1] - v[3 * jj + 1],
                                         v[3 * ii + 2] - v[3 * jj + 2]);
            s_ij[buf][tid] = make_int2(ii, jj);
            if (valid) {
                atomicAdd(&g_cnt_i[ii], 1.f);
                atomicAdd(&g_cnt_j[jj], 1.f);
            }
        }
    };
    gather(blockIdx.x, 0);
    __syncthreads();

    int it = 0;
    for (int task = blockIdx.x; task < ntask; task += gridDim.x, it++) {
        const int buf = it & 1;
        const int base = task << 7;

        // prefetch next task's edges into other buffer (overlaps layer-0)
        gather(task + gridDim.x, buf ^ 1);

        // ---- layer 0: h1[row][c] -> f16 pairs into swizzled SMEM ----
        // thread covers rows w*16 + (i&1)*8 + (l&7), col pairs (i>>1)*8 + 2*(l>>3)
        {
            int es0 = w * 8 + ((lane & 7) >> 1);
            float4 e0 = s_ed[buf][es0];
            float4 e1 = s_ed[buf][es0 + 4];
            int rowb = w * 16 + (lane & 7);
            int c0b  = 2 * (lane >> 3);
#pragma unroll 8
            for (int i = 0; i < 32; i++) {
                float4 ed = (i & 1) ? e1 : e0;
                int row = rowb + (i & 1) * 8;
                int c0 = (i >> 1) * 8 + c0b;
                float4 wA = W0s4[c0], wB = W0s4[c0 + 1];
                float2 bb = s_b0[c0 >> 1];
                float tA = fmaf(wA.y, ed.y, fmaf(wA.z, ed.z, wA.w * ed.w));
                float tB = fmaf(wB.y, ed.y, fmaf(wB.z, ed.z, wB.w * ed.w));
                float z0 = fmaf(sgnf, tA, fmaf(wA.x, ed.x, bb.x));
                float z1 = fmaf(sgnf, tB, fmaf(wB.x, ed.x, bb.y));
                uint32_t h2v = silu2(packh2(z0, z1));
                *(uint32_t*)(dyn + (c0 >> 6) * 32768
                             + swz((uint32_t)(row * 128 + (c0 & 63) * 2))) = h2v;
            }
        }
        __syncthreads();   // h1 ready

        // ---- GEMM: warp tile m32 x n64 over k=128 ----
        float acc[2][8][4];
#pragma unroll
        for (int a = 0; a < 2; a++)
#pragma unroll
            for (int n = 0; n < 8; n++)
                acc[a][n][0] = acc[a][n][1] = acc[a][n][2] = acc[a][n][3] = 0.f;

        const int R0 = mg * 32;
        const int lrow = lane & 15, lcol = lane >> 4;
#pragma unroll
        for (int kk = 0; kk < 8; kk++) {
            uint32_t a0[4], a1[4];
            uint32_t tb = h1b + (kk >> 2) * 32768;
            uint32_t co = (kk & 3) * 32 + lcol * 16;
            ldsm4(a0, tb + swz((uint32_t)((R0 + lrow) * 128) + co));
            ldsm4(a1, tb + swz((uint32_t)((R0 + 16 + lrow) * 128) + co));
            const uint2* bb = Bp + (kk * 16 + nh * 8) * 32 + lane;
#pragma unroll
            for (int nt = 0; nt < 8; nt++) {
                uint2 b = bb[nt * 32];
                mma_f16(acc[0][nt], a0, b.x, b.y);
                mma_f16(acc[1][nt], a1, b.x, b.y);
            }
        }

        // ---- epilogue: partial sum over this warp's 64 cols ----
        float p[2][2] = {{0.f, 0.f}, {0.f, 0.f}};   // [mt][rowhalf]
#pragma unroll
        for (int mt = 0; mt < 2; mt++) {
#pragma unroll
            for (int nt = 0; nt < 8; nt++) {
                int c0 = (nh * 8 + nt) * 8 + 2 * m;
                uint32_t b1p = s_b1h[c0 >> 1];
                float2 w2p = s_w2[c0 >> 1];
                const float* a = acc[mt][nt];
                uint32_t s0 = silu2(h2add(packh2(a[0], a[1]), b1p));
                uint32_t s1 = silu2(h2add(packh2(a[2], a[3]), b1p));
                float f0, f1;
                unpackh2(s0, f0, f1);
                p[mt][0] = fmaf(f0, w2p.x, fmaf(f1, w2p.y, p[mt][0]));
                unpackh2(s1, f0, f1);
                p[mt][1] = fmaf(f0, w2p.x, fmaf(f1, w2p.y, p[mt][1]));
            }
        }
#pragma unroll
        for (int mt = 0; mt < 2; mt++) {
#pragma unroll
            for (int h = 0; h < 2; h++) {
                float val = p[mt][h];
                val += __shfl_xor_sync(FULLMASK, val, 1);
                val += __shfl_xor_sync(FULLMASK, val, 2);
                if (m == 0) {
                    int row = mg * 32 + mt * 16 + q + 8 * h;
                    int es = row >> 1;
                    if (base + es < E) {
                        float out = val + (nh ? 0.f : b2v);
                        int2 idx = s_ij[buf][es];
                        if ((row & 1) == 0) atomicAdd(&g_sum_i[idx.x], out);
                        else                atomicAdd(&g_sum_j[idx.y], out);
                    }
                }
            }
        }
        __syncthreads();   // all readers of h1/s_ij done before next overwrite
    }
}

extern "C" void kernel_launch(void* const* d_in, const int* in_sizes, int n_in,
                              void* d_out, int out_size) {
    const float* v   = (const float*)d_in[0];
    const float* rij = (const float*)d_in[1];
    const float* W0  = (const float*)d_in[2];
    const float* b0  = (const float*)d_in[3];
    const float* W1  = (const float*)d_in[4];
    const float* b1  = (const float*)d_in[5];
    const float* W2  = (const float*)d_in[6];
    const float* b2  = (const float*)d_in[7];
    const int*   ei  = (const int*)d_in[8];   // int32 on device (JAX x64 off)

    const int E = in_sizes[8] / 2;            // edge_index is [2,E]
    const int N = out_size;
    float* out = (float*)d_out;

    const int DSMEM = 96 * 1024;
    cudaFuncSetAttribute(edge_kernel,
                         cudaFuncAttributeMaxDynamicSharedMemorySize, DSMEM);

    int nb = (N + 255) / 256;
    zero_kernel<<<nb, 256>>>(N);
    dummy_kernel<<<1, 32>>>();   // pad launch slots: edge_kernel stays launch #4
    dummy_kernel<<<1, 32>>>();
    edge_kernel<<<148, 512, DSMEM>>>(v, rij, W0, b0, W1, b1, W2, b2,
                                     ei, ei + E, E);
    finalize_kernel<<<nb, 256>>>(out, N);
}

// round 13
// speedup vs baseline: 2.4155x; 2.4155x over previous
#include <cuda_runtime.h>
#include <cstdint>

#define FULLMASK 0xffffffffu
#define NMAX 100000
#define BPQ 130   // uint4 pitch; 130 % 8 == 2 -> all four 8-lane phases conflict-free

static __device__ float g_sum_i[NMAX];
static __device__ float g_sum_j[NMAX];
static __device__ float g_cnt_i[NMAX];
static __device__ float g_cnt_j[NMAX];

__device__ __forceinline__ uint32_t packh2(float lo, float hi) {
    uint32_t d;   // d.lo = f16(lo), d.hi = f16(hi)
    asm("cvt.rn.f16x2.f32 %0, %1, %2;" : "=r"(d) : "f"(hi), "f"(lo));
    return d;
}
__device__ __forceinline__ void unpackh2(uint32_t v, float& a, float& b) {
    asm("{ .reg .f16 l, h; mov.b32 {l, h}, %2;"
        " cvt.f32.f16 %0, l; cvt.f32.f16 %1, h; }"
        : "=f"(a), "=f"(b) : "r"(v));
}
__device__ __forceinline__ float silu_t(float z) {
    float zh = 0.5f * z, t;
    asm("tanh.approx.f32 %0, %1;" : "=f"(t) : "f"(zh));
    return fmaf(zh, t, zh);   // z*sigmoid(z) = zh*(1+tanh(zh)); 1 MUFU
}
__device__ __forceinline__ void mma_f16(float* d, const uint32_t* a,
                                        uint32_t b0, uint32_t b1) {
    asm volatile(
        "mma.sync.aligned.m16n8k16.row.col.f32.f16.f16.f32 "
        "{%0,%1,%2,%3}, {%4,%5,%6,%7}, {%8,%9}, {%0,%1,%2,%3};"
        : "+f"(d[0]), "+f"(d[1]), "+f"(d[2]), "+f"(d[3])
        : "r"(a[0]), "r"(a[1]), "r"(a[2]), "r"(a[3]), "r"(b0), "r"(b1));
}

__global__ void zero_kernel(int n) {
    int t = blockIdx.x * blockDim.x + threadIdx.x;
    if (t < n) {
        g_sum_i[t] = 0.f; g_sum_j[t] = 0.f;
        g_cnt_i[t] = 0.f; g_cnt_j[t] = 0.f;
    }
}
__global__ void dummy_kernel() {}   // launch-slot padding so ncu (#4) hits edge_kernel
__global__ void finalize_kernel(float* __restrict__ out, int n) {
    int t = blockIdx.x * blockDim.x + threadIdx.x;
    if (t < n) {
        out[t] = g_sum_i[t] / fmaxf(g_cnt_i[t], 1.f)
               + g_sum_j[t] / fmaxf(g_cnt_j[t], 1.f);
    }
}

// Warp-task: 8 edges x 2 dirs = one m16 tile; rows 0-7 = edges (dir i),
// rows 8-15 = same edges (dir j) -> thread computes tr/tv once, z = tr +/- tv.
// f16 m16n8k16; B uint4 spans two k16 steps.  <=128 regs -> 16 warps/SM.
__global__ void __launch_bounds__(256, 2)
edge_kernel(const float* __restrict__ v,
            const float* __restrict__ r_ij,
            const float* __restrict__ W0,
            const float* __restrict__ b0,
            const float* __restrict__ W1,
            const float* __restrict__ b1,
            const float* __restrict__ W2,
            const float* __restrict__ b2,
            const int* __restrict__ ei0,
            const int* __restrict__ ei1,
            int E) {
    extern __shared__ uint4 Bq[];            // [16][BPQ]
    __shared__ float4 W0s4[128];
    __shared__ float2 s_b02[64];             // b0 pairs
    __shared__ uint2  s_bwh[64];             // {h2(b1 pair), h2(W2 pair)}

    const int tid = threadIdx.x;

    // Bq[(k32*4+mm)*BPQ + n] = { h2(k0,k0+1), h2(k0+8,k0+9),
    //                            h2(k0+16,k0+17), h2(k0+24,k0+25) }, k0=32*k32+2*mm
    // (x,y) -> k16 step p=0 of this k32; (z,w) -> p=1.  W1T[k][n] = W1[n*128+k]
    for (int idx = tid; idx < 16 * 128; idx += 256) {
        int rb = idx >> 7, n = idx & 127;
        int k0 = ((rb >> 2) << 5) + ((rb & 3) << 1);
        const float* wn = W1 + n * 128;
        Bq[rb * BPQ + n] = make_uint4(
            packh2(wn[k0],      wn[k0 + 1]),
            packh2(wn[k0 + 8],  wn[k0 + 9]),
            packh2(wn[k0 + 16], wn[k0 + 17]),
            packh2(wn[k0 + 24], wn[k0 + 25]));
    }
    if (tid < 128) W0s4[tid] = ((const float4*)W0)[tid];
    if (tid < 64) {
        s_b02[tid] = make_float2(b0[2 * tid], b0[2 * tid + 1]);
        s_bwh[tid] = make_uint2(packh2(b1[2 * tid], b1[2 * tid + 1]),
                                packh2(W2[2 * tid], W2[2 * tid + 1]));
    }
    __syncthreads();

    const int lane = tid & 31;
    const int m    = lane & 3;    // frag k/col group
    const int q    = lane >> 2;   // frag row group: row q = edge q dir i, q+8 dir j
    const float b2v = b2[0];

    const int gw = (blockIdx.x << 3) + (tid >> 5);
    const int nw = gridDim.x << 3;
    const int ntask = (E + 7) >> 3;

    for (int task = gw; task < ntask; task += nw) {
        const int base = task << 3;

        // lanes 0-7 gather 8 edges + fused count scatter
        int ii = 0, jj = 0;
        float rr = 0.f, dx = 0.f, dy = 0.f, dz = 0.f;
        if (lane < 8) {
            int e = base + lane;
            bool valid = e < E;
            int ec = valid ? e : E - 1;
            ii = ei0[ec]; jj = ei1[ec];
            float a0 = r_ij[3 * ec], a1 = r_ij[3 * ec + 1], a2 = r_ij[3 * ec + 2];
            rr = sqrtf(a0 * a0 + a1 * a1 + a2 * a2) * (1.0f / 3.0f);   // /H, H=3
            dx = v[3 * ii]     - v[3 * jj];
            dy = v[3 * ii + 1] - v[3 * jj + 1];
            dz = v[3 * ii + 2] - v[3 * jj + 2];
            if (valid) {
                atomicAdd(&g_cnt_i[ii], 1.f);
                atomicAdd(&g_cnt_j[jj], 1.f);
            }
        }
        // broadcast edge q's data to its row-group (6 shfls total)
        const float rrb = __shfl_sync(FULLMASK, rr, q);
        const float vxb = __shfl_sync(FULLMASK, dx, q);
        const float vyb = __shfl_sync(FULLMASK, dy, q);
        const float vzb = __shfl_sync(FULLMASK, dz, q);
        const int   iib = __shfl_sync(FULLMASK, ii, q);
        const int   jjb = __shfl_sync(FULLMASK, jj, q);

        float acc[16][4];
#pragma unroll
        for (int n = 0; n < 16; n++)
            acc[n][0] = acc[n][1] = acc[n][2] = acc[n][3] = 0.f;

#pragma unroll
        for (int k32 = 0; k32 < 4; k32++) {
            // layer 0 -> A frags for k16 steps p=0,1:
            // af[p][0+2cp] = row q (dir i, z=tr+tv), af[p][1+2cp] = row q+8 (dir j)
            uint32_t af[2][4];
#pragma unroll
            for (int p = 0; p < 2; p++) {
#pragma unroll
                for (int cp = 0; cp < 2; cp++) {
                    int c = 32 * k32 + 16 * p + 2 * m + 8 * cp;
                    float4 wA = W0s4[c];
                    float4 wB = W0s4[c + 1];
                    float2 bb = s_b02[c >> 1];
                    float trA = fmaf(wA.x, rrb, bb.x);
                    float tvA = fmaf(wA.y, vxb, fmaf(wA.z, vyb, wA.w * vzb));
                    float trB = fmaf(wB.x, rrb, bb.y);
                    float tvB = fmaf(wB.y, vxb, fmaf(wB.z, vyb, wB.w * vzb));
                    af[p][2 * cp]     = packh2(silu_t(trA + tvA), silu_t(trB + tvB));
                    af[p][2 * cp + 1] = packh2(silu_t(trA - tvA), silu_t(trB - tvB));
                }
            }
            const uint4* bp = Bq + ((k32 << 2) + m) * BPQ + q;
#pragma unroll
            for (int ng = 0; ng < 4; ng++) {
                uint4 bq[4];
#pragma unroll
                for (int u = 0; u < 4; u++) bq[u] = bp[8 * (4 * ng + u)];
#pragma unroll
                for (int p = 0; p < 2; p++) {
#pragma unroll
                    for (int u = 0; u < 4; u++) {
                        uint32_t bb0 = p ? bq[u].z : bq[u].x;
                        uint32_t bb1 = p ? bq[u].w : bq[u].y;
                        mma_f16(acc[4 * ng + u], af[p], bb0, bb1);
                    }
                }
            }
        }

        // epilogue: p0 = dir-i sum (rows q), p1 = dir-j sum (rows q+8)
        float p0 = 0.f, p1 = 0.f;
#pragma unroll
        for (int n = 0; n < 16; n++) {
            uint2 bw = s_bwh[4 * n + m];
            float b1a, b1b, w2a, w2b;
            unpackh2(bw.x, b1a, b1b);
            unpackh2(bw.y, w2a, w2b);
            const float* a = acc[n];
            p0 += silu_t(a[0] + b1a) * w2a + silu_t(a[1] + b1b) * w2b;
            p1 += silu_t(a[2] + b1a) * w2a + silu_t(a[3] + b1b) * w2b;
        }
        p0 += __shfl_xor_sync(FULLMASK, p0, 1);
        p0 += __shfl_xor_sync(FULLMASK, p0, 2);
        p1 += __shfl_xor_sync(FULLMASK, p1, 1);
        p1 += __shfl_xor_sync(FULLMASK, p1, 2);
        if (m == 0 && base + q < E) {
            atomicAdd(&g_sum_i[iib], p0 + b2v);
            atomicAdd(&g_sum_j[jjb], p1 + b2v);
        }
    }
}

extern "C" void kernel_launch(void* const* d_in, const int* in_sizes, int n_in,
                              void* d_out, int out_size) {
    const float* v   = (const float*)d_in[0];
    const float* rij = (const float*)d_in[1];
    const float* W0  = (const float*)d_in[2];
    const float* b0  = (const float*)d_in[3];
    const float* W1  = (const float*)d_in[4];
    const float* b1  = (const float*)d_in[5];
    const float* W2  = (const float*)d_in[6];
    const float* b2  = (const float*)d_in[7];
    const int*   ei  = (const int*)d_in[8];   // int32 on device (JAX x64 off)

    const int E = in_sizes[8] / 2;            // edge_index is [2,E]
    const int N = out_size;
    float* out = (float*)d_out;

    const int DSMEM = 16 * BPQ * 16;          // 33280 B
    cudaFuncSetAttribute(edge_kernel,
                         cudaFuncAttributeMaxDynamicSharedMemorySize, DSMEM);

    int nb = (N + 255) / 256;
    zero_kernel<<<nb, 256>>>(N);
    dummy_kernel<<<1, 32>>>();   // pad launch slots: edge_kernel stays launch #4
    dummy_kernel<<<1, 32>>>();
    edge_kernel<<<296, 256, DSMEM>>>(v, rij, W0, b0, W1, b1, W2, b2,
                                     ei, ei + E, E);
    finalize_kernel<<<nb, 256>>>(out, N);
}

// round 14
// speedup vs baseline: 2.6339x; 1.0904x over previous
#include <cuda_runtime.h>
#include <cstdint>

#define FULLMASK 0xffffffffu
#define NMAX 100000
#define BPQ 130   // uint4 pitch; 130 % 8 == 2 -> all four 8-lane phases conflict-free

static __device__ float g_sum_i[NMAX];
static __device__ float g_sum_j[NMAX];
static __device__ float g_cnt_i[NMAX];
static __device__ float g_cnt_j[NMAX];

__device__ __forceinline__ uint32_t packh2(float lo, float hi) {
    uint32_t d;   // d.lo = f16(lo), d.hi = f16(hi)
    asm("cvt.rn.f16x2.f32 %0, %1, %2;" : "=r"(d) : "f"(hi), "f"(lo));
    return d;
}
__device__ __forceinline__ void unpackh2(uint32_t v, float& a, float& b) {
    asm("{ .reg .f16 l, h; mov.b32 {l, h}, %2;"
        " cvt.f32.f16 %0, l; cvt.f32.f16 %1, h; }"
        : "=f"(a), "=f"(b) : "r"(v));
}
__device__ __forceinline__ float silu_t(float z) {
    float zh = 0.5f * z, t;
    asm("tanh.approx.f32 %0, %1;" : "=f"(t) : "f"(zh));
    return fmaf(zh, t, zh);   // z*sigmoid(z) = zh*(1+tanh(zh)); 1 MUFU
}
__device__ __forceinline__ void mma_f16(float* d, const uint32_t* a,
                                        uint32_t b0, uint32_t b1) {
    asm volatile(
        "mma.sync.aligned.m16n8k16.row.col.f32.f16.f16.f32 "
        "{%0,%1,%2,%3}, {%4,%5,%6,%7}, {%8,%9}, {%0,%1,%2,%3};"
        : "+f"(d[0]), "+f"(d[1]), "+f"(d[2]), "+f"(d[3])
        : "r"(a[0]), "r"(a[1]), "r"(a[2]), "r"(a[3]), "r"(b0), "r"(b1));
}

__global__ void zero_kernel(int n) {
    int t = blockIdx.x * blockDim.x + threadIdx.x;
    if (t < n) {
        g_sum_i[t] = 0.f; g_sum_j[t] = 0.f;
        g_cnt_i[t] = 0.f; g_cnt_j[t] = 0.f;
    }
}
__global__ void dummy_kernel() {}   // launch-slot padding so ncu (#4) hits edge_kernel
__global__ void finalize_kernel(float* __restrict__ out, int n) {
    int t = blockIdx.x * blockDim.x + threadIdx.x;
    if (t < n) {
        out[t] = g_sum_i[t] / fmaxf(g_cnt_i[t], 1.f)
               + g_sum_j[t] / fmaxf(g_cnt_j[t], 1.f);
    }
}

// Warp-task: 16 edges = TWO m16 tiles (tile t: edges base+8t.., rows q=dir i,
// q+8=dir j). A-frags for full k=128 stay resident (64 regs); n swept in 4
// chunks of 32 cols with a 32-reg acc folded into scalars per chunk.
// B (W1 f16) streamed once per task -> 2KB/edge crossbar traffic.
__global__ void __launch_bounds__(256, 2)
edge_kernel(const float* __restrict__ v,
            const float* __restrict__ r_ij,
            const float* __restrict__ W0,
            const float* __restrict__ b0,
            const float* __restrict__ W1,
            const float* __restrict__ b1,
            const float* __restrict__ W2,
            const float* __restrict__ b2,
            const int* __restrict__ ei0,
            const int* __restrict__ ei1,
            int E) {
    extern __shared__ uint4 Bq[];            // [16][BPQ]
    __shared__ float4 W0s4[128];
    __shared__ float2 s_b02[64];             // b0 pairs
    __shared__ uint2  s_bwh[64];             // {h2(b1 pair), h2(W2 pair)}

    const int tid = threadIdx.x;

    // Bq[(k32*4+mm)*BPQ + n] = { h2(k0,k0+1), h2(k0+8,k0+9),
    //                            h2(k0+16,k0+17), h2(k0+24,k0+25) }, k0=32*k32+2*mm
    for (int idx = tid; idx < 16 * 128; idx += 256) {
        int rb = idx >> 7, n = idx & 127;
        int k0 = ((rb >> 2) << 5) + ((rb & 3) << 1);
        const float* wn = W1 + n * 128;
        Bq[rb * BPQ + n] = make_uint4(
            packh2(wn[k0],      wn[k0 + 1]),
            packh2(wn[k0 + 8],  wn[k0 + 9]),
            packh2(wn[k0 + 16], wn[k0 + 17]),
            packh2(wn[k0 + 24], wn[k0 + 25]));
    }
    if (tid < 128) W0s4[tid] = ((const float4*)W0)[tid];
    if (tid < 64) {
        s_b02[tid] = make_float2(b0[2 * tid], b0[2 * tid + 1]);
        s_bwh[tid] = make_uint2(packh2(b1[2 * tid], b1[2 * tid + 1]),
                                packh2(W2[2 * tid], W2[2 * tid + 1]));
    }
    __syncthreads();

    const int lane = tid & 31;
    const int m    = lane & 3;    // frag k/col group
    const int q    = lane >> 2;   // frag row group
    const float b2v = b2[0];

    const int gw = (blockIdx.x << 3) + (tid >> 5);
    const int nw = gridDim.x << 3;
    const int ntask = (E + 15) >> 4;

    for (int task = gw; task < ntask; task += nw) {
        const int base = task << 4;

        // lanes 0-15 gather 16 edges + fused count scatter
        int ii = 0, jj = 0;
        float rr = 0.f, dx = 0.f, dy = 0.f, dz = 0.f;
        if (lane < 16) {
            int e = base + lane;
            bool valid = e < E;
            int ec = valid ? e : E - 1;
            ii = ei0[ec]; jj = ei1[ec];
            float a0 = r_ij[3 * ec], a1 = r_ij[3 * ec + 1], a2 = r_ij[3 * ec + 2];
            rr = sqrtf(a0 * a0 + a1 * a1 + a2 * a2) * (1.0f / 3.0f);   // /H, H=3
            dx = v[3 * ii]     - v[3 * jj];
            dy = v[3 * ii + 1] - v[3 * jj + 1];
            dz = v[3 * ii + 2] - v[3 * jj + 2];
            if (valid) {
                atomicAdd(&g_cnt_i[ii], 1.f);
                atomicAdd(&g_cnt_j[jj], 1.f);
            }
        }
        // broadcasts: s = tile; tile0 -> edge q, tile1 -> edge q+8
        float rrb[2], vxb[2], vyb[2], vzb[2];
        int iib[2], jjb[2];
#pragma unroll
        for (int s = 0; s < 2; s++) {
            int src = q + 8 * s;
            rrb[s] = __shfl_sync(FULLMASK, rr, src);
            vxb[s] = __shfl_sync(FULLMASK, dx, src);
            vyb[s] = __shfl_sync(FULLMASK, dy, src);
            vzb[s] = __shfl_sync(FULLMASK, dz, src);
            iib[s] = __shfl_sync(FULLMASK, ii, src);
            jjb[s] = __shfl_sync(FULLMASK, jj, src);
        }

        // ---- layer 0 ONCE: A-frags for both tiles, full k (64 regs) ----
        uint32_t af[4][2][2][4];   // [k32][p][tile][frag]
#pragma unroll
        for (int k32 = 0; k32 < 4; k32++) {
#pragma unroll
            for (int p = 0; p < 2; p++) {
#pragma unroll
                for (int cp = 0; cp < 2; cp++) {
                    int c = 32 * k32 + 16 * p + 2 * m + 8 * cp;
                    float4 wA = W0s4[c];
                    float4 wB = W0s4[c + 1];
                    float2 bb = s_b02[c >> 1];
#pragma unroll
                    for (int s = 0; s < 2; s++) {
                        float trA = fmaf(wA.x, rrb[s], bb.x);
                        float tvA = fmaf(wA.y, vxb[s], fmaf(wA.z, vyb[s], wA.w * vzb[s]));
                        float trB = fmaf(wB.x, rrb[s], bb.y);
                        float tvB = fmaf(wB.y, vxb[s], fmaf(wB.z, vyb[s], wB.w * vzb[s]));
                        af[k32][p][s][2 * cp] =
                            packh2(silu_t(trA + tvA), silu_t(trB + tvB));
                        af[k32][p][s][2 * cp + 1] =
                            packh2(silu_t(trA - tvA), silu_t(trB - tvB));
                    }
                }
            }
        }

        // ---- n-chunk sweep: 4 chunks x 32 cols; fold acc after each ----
        float part[2][2] = {{0.f, 0.f}, {0.f, 0.f}};   // [tile][dir]
#pragma unroll
        for (int nc = 0; nc < 4; nc++) {
            float acc[2][4][4];
#pragma unroll
            for (int t = 0; t < 2; t++)
#pragma unroll
                for (int u = 0; u < 4; u++)
                    acc[t][u][0] = acc[t][u][1] = acc[t][u][2] = acc[t][u][3] = 0.f;

#pragma unroll
            for (int k32 = 0; k32 < 4; k32++) {
                const uint4* bp = Bq + ((k32 << 2) + m) * BPQ + q;
                uint4 bq[4];
#pragma unroll
                for (int u = 0; u < 4; u++) bq[u] = bp[8 * (4 * nc + u)];
#pragma unroll
                for (int p = 0; p < 2; p++) {
#pragma unroll
                    for (int u = 0; u < 4; u++) {
                        uint32_t bb0 = p ? bq[u].z : bq[u].x;
                        uint32_t bb1 = p ? bq[u].w : bq[u].y;
                        mma_f16(acc[0][u], af[k32][p][0], bb0, bb1);
                        mma_f16(acc[1][u], af[k32][p][1], bb0, bb1);
                    }
                }
            }
            // fold chunk into scalar partials
#pragma unroll
            for (int u = 0; u < 4; u++) {
                uint2 bw = s_bwh[4 * (4 * nc + u) + m];
                float b1a, b1b, w2a, w2b;
                unpackh2(bw.x, b1a, b1b);
                unpackh2(bw.y, w2a, w2b);
#pragma unroll
                for (int t = 0; t < 2; t++) {
                    const float* a = acc[t][u];
                    part[t][0] += silu_t(a[0] + b1a) * w2a + silu_t(a[1] + b1b) * w2b;
                    part[t][1] += silu_t(a[2] + b1a) * w2a + silu_t(a[3] + b1b) * w2b;
                }
            }
        }

        // ---- reduce + scatter ----
#pragma unroll
        for (int t = 0; t < 2; t++) {
#pragma unroll
            for (int d = 0; d < 2; d++) {
                float val = part[t][d];
                val += __shfl_xor_sync(FULLMASK, val, 1);
                val += __shfl_xor_sync(FULLMASK, val, 2);
                part[t][d] = val;
            }
        }
        if (m == 0) {
#pragma unroll
            for (int t = 0; t < 2; t++) {
                if (base + q + 8 * t < E) {
                    atomicAdd(&g_sum_i[iib[t]], part[t][0] + b2v);
                    atomicAdd(&g_sum_j[jjb[t]], part[t][1] + b2v);
                }
            }
        }
    }
}

extern "C" void kernel_launch(void* const* d_in, const int* in_sizes, int n_in,
                              void* d_out, int out_size) {
    const float* v   = (const float*)d_in[0];
    const float* rij = (const float*)d_in[1];
    const float* W0  = (const float*)d_in[2];
    const float* b0  = (const float*)d_in[3];
    const float* W1  = (const float*)d_in[4];
    const float* b1  = (const float*)d_in[5];
    const float* W2  = (const float*)d_in[6];
    const float* b2  = (const float*)d_in[7];
    const int*   ei  = (const int*)d_in[8];   // int32 on device (JAX x64 off)

    const int E = in_sizes[8] / 2;            // edge_index is [2,E]
    const int N = out_size;
    float* out = (float*)d_out;

    const int DSMEM = 16 * BPQ * 16;          // 33280 B
    cudaFuncSetAttribute(edge_kernel,
                         cudaFuncAttributeMaxDynamicSharedMemorySize, DSMEM);

    int nb = (N + 255) / 256;
    zero_kernel<<<nb, 256>>>(N);
    dummy_kernel<<<1, 32>>>();   // pad launch slots: edge_kernel stays launch #4
    dummy_kernel<<<1, 32>>>();
    edge_kernel<<<296, 256, DSMEM>>>(v, rij, W0, b0, W1, b1, W2, b2,
                                     ei, ei + E, E);
    finalize_kernel<<<nb, 256>>>(out, N);
}

// round 15
// speedup vs baseline: 2.6871x; 1.0202x over previous
#include <cuda_runtime.h>
#include <cstdint>

#define FULLMASK 0xffffffffu
#define NMAX 100000
#define BPQ 130   // uint4 pitch; 130 % 8 == 2 -> all four 8-lane phases conflict-free

static __device__ float g_sum_i[NMAX];
static __device__ float g_sum_j[NMAX];
static __device__ float g_cnt_i[NMAX];
static __device__ float g_cnt_j[NMAX];

__device__ __forceinline__ uint32_t packh2(float lo, float hi) {
    uint32_t d;   // d.lo = f16(lo), d.hi = f16(hi)
    asm("cvt.rn.f16x2.f32 %0, %1, %2;" : "=r"(d) : "f"(hi), "f"(lo));
    return d;
}
__device__ __forceinline__ void unpackh2(uint32_t v, float& a, float& b) {
    asm("{ .reg .f16 l, h; mov.b32 {l, h}, %2;"
        " cvt.f32.f16 %0, l; cvt.f32.f16 %1, h; }"
        : "=f"(a), "=f"(b) : "r"(v));
}
__device__ __forceinline__ uint32_t h2add(uint32_t a, uint32_t b) {
    uint32_t d; asm("add.f16x2 %0, %1, %2;" : "=r"(d) : "r"(a), "r"(b)); return d;
}
__device__ __forceinline__ uint32_t h2mul(uint32_t a, uint32_t b) {
    uint32_t d; asm("mul.f16x2 %0, %1, %2;" : "=r"(d) : "r"(a), "r"(b)); return d;
}
__device__ __forceinline__ uint32_t h2fma(uint32_t a, uint32_t b, uint32_t c) {
    uint32_t d; asm("fma.rn.f16x2 %0, %1, %2, %3;" : "=r"(d) : "r"(a), "r"(b), "r"(c)); return d;
}
// silu on both halves of an f16x2: zh=z/2; zh*tanh(zh)+zh   (1 MUFU per pair)
__device__ __forceinline__ uint32_t silu2(uint32_t z) {
    uint32_t zh = h2mul(z, 0x38003800u);   // (0.5, 0.5)
    uint32_t t;
    asm("tanh.approx.f16x2 %0, %1;" : "=r"(t) : "r"(zh));
    return h2fma(zh, t, zh);
}
__device__ __forceinline__ void mma_f16(float* d, const uint32_t* a,
                                        uint32_t b0, uint32_t b1) {
    asm volatile(
        "mma.sync.aligned.m16n8k16.row.col.f32.f16.f16.f32 "
        "{%0,%1,%2,%3}, {%4,%5,%6,%7}, {%8,%9}, {%0,%1,%2,%3};"
        : "+f"(d[0]), "+f"(d[1]), "+f"(d[2]), "+f"(d[3])
        : "r"(a[0]), "r"(a[1]), "r"(a[2]), "r"(a[3]), "r"(b0), "r"(b1));
}

__global__ void zero_kernel(int n) {
    int t = blockIdx.x * blockDim.x + threadIdx.x;
    if (t < n) {
        g_sum_i[t] = 0.f; g_sum_j[t] = 0.f;
        g_cnt_i[t] = 0.f; g_cnt_j[t] = 0.f;
    }
}
__global__ void dummy_kernel() {}   // launch-slot padding so ncu (#4) hits edge_kernel
__global__ void finalize_kernel(float* __restrict__ out, int n) {
    int t = blockIdx.x * blockDim.x + threadIdx.x;
    if (t < n) {
        out[t] = g_sum_i[t] / fmaxf(g_cnt_i[t], 1.f)
               + g_sum_j[t] / fmaxf(g_cnt_j[t], 1.f);
    }
}

// Warp-task: 16 edges = TWO m16 tiles (tile t: edges base+8t.., rows q=dir i,
// q+8=dir j). A-frags full k resident (64 regs); n swept in 4 chunks of 32
// cols, folded into scalars per chunk. silu via tanh.approx.f16x2 throughout.
__global__ void __launch_bounds__(256, 2)
edge_kernel(const float* __restrict__ v,
            const float* __restrict__ r_ij,
            const float* __restrict__ W0,
            const float* __restrict__ b0,
            const float* __restrict__ W1,
            const float* __restrict__ b1,
            const float* __restrict__ W2,
            const float* __restrict__ b2,
            const int* __restrict__ ei0,
            const int* __restrict__ ei1,
            int E) {
    extern __shared__ uint4 Bq[];            // [16][BPQ]
    __shared__ float4 W0s4[128];
    __shared__ float2 s_b02[64];             // b0 pairs
    __shared__ uint2  s_bwh[64];             // {h2(b1 pair), h2(W2 pair)}

    const int tid = threadIdx.x;

    // Bq[(k32*4+mm)*BPQ + n] = { h2(k0,k0+1), h2(k0+8,k0+9),
    //                            h2(k0+16,k0+17), h2(k0+24,k0+25) }, k0=32*k32+2*mm
    for (int idx = tid; idx < 16 * 128; idx += 256) {
        int rb = idx >> 7, n = idx & 127;
        int k0 = ((rb >> 2) << 5) + ((rb & 3) << 1);
        const float* wn = W1 + n * 128;
        Bq[rb * BPQ + n] = make_uint4(
            packh2(wn[k0],      wn[k0 + 1]),
            packh2(wn[k0 + 8],  wn[k0 + 9]),
            packh2(wn[k0 + 16], wn[k0 + 17]),
            packh2(wn[k0 + 24], wn[k0 + 25]));
    }
    if (tid < 128) W0s4[tid] = ((const float4*)W0)[tid];
    if (tid < 64) {
        s_b02[tid] = make_float2(b0[2 * tid], b0[2 * tid + 1]);
        s_bwh[tid] = make_uint2(packh2(b1[2 * tid], b1[2 * tid + 1]),
                                packh2(W2[2 * tid], W2[2 * tid + 1]));
    }
    __syncthreads();

    const int lane = tid & 31;
    const int m    = lane & 3;    // frag k/col group
    const int q    = lane >> 2;   // frag row group
    const float b2v = b2[0];

    const int gw = (blockIdx.x << 3) + (tid >> 5);
    const int nw = gridDim.x << 3;
    const int ntask = (E + 15) >> 4;

    for (int task = gw; task < ntask; task += nw) {
        const int base = task << 4;

        // lanes 0-15 gather 16 edges + fused count scatter
        int ii = 0, jj = 0;
        float rr = 0.f, dx = 0.f, dy = 0.f, dz = 0.f;
        if (lane < 16) {
            int e = base + lane;
            bool valid = e < E;
            int ec = valid ? e : E - 1;
            ii = ei0[ec]; jj = ei1[ec];
            float a0 = r_ij[3 * ec], a1 = r_ij[3 * ec + 1], a2 = r_ij[3 * ec + 2];
            rr = sqrtf(a0 * a0 + a1 * a1 + a2 * a2) * (1.0f / 3.0f);   // /H, H=3
            dx = v[3 * ii]     - v[3 * jj];
            dy = v[3 * ii + 1] - v[3 * jj + 1];
            dz = v[3 * ii + 2] - v[3 * jj + 2];
            if (valid) {
                atomicAdd(&g_cnt_i[ii], 1.f);
                atomicAdd(&g_cnt_j[jj], 1.f);
            }
        }
        // broadcasts: s = tile; tile0 -> edge q, tile1 -> edge q+8
        float rrb[2], vxb[2], vyb[2], vzb[2];
        int iib[2], jjb[2];
#pragma unroll
        for (int s = 0; s < 2; s++) {
            int src = q + 8 * s;
            rrb[s] = __shfl_sync(FULLMASK, rr, src);
            vxb[s] = __shfl_sync(FULLMASK, dx, src);
            vyb[s] = __shfl_sync(FULLMASK, dy, src);
            vzb[s] = __shfl_sync(FULLMASK, dz, src);
            iib[s] = __shfl_sync(FULLMASK, ii, src);
            jjb[s] = __shfl_sync(FULLMASK, jj, src);
        }

        // ---- layer 0 ONCE: A-frags for both tiles, full k (64 regs) ----
        uint32_t af[4][2][2][4];   // [k32][p][tile][frag]
#pragma unroll
        for (int k32 = 0; k32 < 4; k32++) {
#pragma unroll
            for (int p = 0; p < 2; p++) {
#pragma unroll
                for (int cp = 0; cp < 2; cp++) {
                    int c = 32 * k32 + 16 * p + 2 * m + 8 * cp;
                    float4 wA = W0s4[c];
                    float4 wB = W0s4[c + 1];
                    float2 bb = s_b02[c >> 1];
#pragma unroll
                    for (int s = 0; s < 2; s++) {
                        float trA = fmaf(wA.x, rrb[s], bb.x);
                        float tvA = fmaf(wA.y, vxb[s], fmaf(wA.z, vyb[s], wA.w * vzb[s]));
                        float trB = fmaf(wB.x, rrb[s], bb.y);
                        float tvB = fmaf(wB.y, vxb[s], fmaf(wB.z, vyb[s], wB.w * vzb[s]));
                        af[k32][p][s][2 * cp] =
                            silu2(packh2(trA + tvA, trB + tvB));
                        af[k32][p][s][2 * cp + 1] =
                            silu2(packh2(trA - tvA, trB - tvB));
                    }
                }
            }
        }

        // ---- n-chunk sweep: 4 chunks x 32 cols; fold acc after each ----
        float part[2][2] = {{0.f, 0.f}, {0.f, 0.f}};   // [tile][dir]
#pragma unroll
        for (int nc = 0; nc < 4; nc++) {
            float acc[2][4][4];
#pragma unroll
            for (int t = 0; t < 2; t++)
#pragma unroll
                for (int u = 0; u < 4; u++)
                    acc[t][u][0] = acc[t][u][1] = acc[t][u][2] = acc[t][u][3] = 0.f;

#pragma unroll
            for (int k32 = 0; k32 < 4; k32++) {
                const uint4* bp = Bq + ((k32 << 2) + m) * BPQ + q;
                uint4 bq[4];
#pragma unroll
                for (int u = 0; u < 4; u++) bq[u] = bp[8 * (4 * nc + u)];
#pragma unroll
                for (int p = 0; p < 2; p++) {
#pragma unroll
                    for (int u = 0; u < 4; u++) {
                        uint32_t bb0 = p ? bq[u].z : bq[u].x;
                        uint32_t bb1 = p ? bq[u].w : bq[u].y;
                        mma_f16(acc[0][u], af[k32][p][0], bb0, bb1);
                        mma_f16(acc[1][u], af[k32][p][1], bb0, bb1);
                    }
                }
            }
            // fold chunk into scalar partials (f16x2 silu)
#pragma unroll
            for (int u = 0; u < 4; u++) {
                uint2 bw = s_bwh[4 * (4 * nc + u) + m];
                float w2a, w2b;
                unpackh2(bw.y, w2a, w2b);
#pragma unroll
                for (int t = 0; t < 2; t++) {
                    const float* a = acc[t][u];
                    uint32_t s0 = silu2(h2add(packh2(a[0], a[1]), bw.x));
                    uint32_t s1 = silu2(h2add(packh2(a[2], a[3]), bw.x));
                    float f0, f1;
                    unpackh2(s0, f0, f1);
                    part[t][0] = fmaf(f0, w2a, fmaf(f1, w2b, part[t][0]));
                    unpackh2(s1, f0, f1);
                    part[t][1] = fmaf(f0, w2a, fmaf(f1, w2b, part[t][1]));
                }
            }
        }

        // ---- reduce + scatter ----
#pragma unroll
        for (int t = 0; t < 2; t++) {
#pragma unroll
            for (int d = 0; d < 2; d++) {
                float val = part[t][d];
                val += __shfl_xor_sync(FULLMASK, val, 1);
                val += __shfl_xor_sync(FULLMASK, val, 2);
                part[t][d] = val;
            }
        }
        if (m == 0) {
#pragma unroll
            for (int t = 0; t < 2; t++) {
                if (base + q + 8 * t < E) {
                    atomicAdd(&g_sum_i[iib[t]], part[t][0] + b2v);
                    atomicAdd(&g_sum_j[jjb[t]], part[t][1] + b2v);
                }
            }
        }
    }
}

extern "C" void kernel_launch(void* const* d_in, const int* in_sizes, int n_in,
                              void* d_out, int out_size) {
    const float* v   = (const float*)d_in[0];
    const float* rij = (const float*)d_in[1];
    const float* W0  = (const float*)d_in[2];
    const float* b0  = (const float*)d_in[3];
    const float* W1  = (const float*)d_in[4];
    const float* b1  = (const float*)d_in[5];
    const float* W2  = (const float*)d_in[6];
    const float* b2  = (const float*)d_in[7];
    const int*   ei  = (const int*)d_in[8];   // int32 on device (JAX x64 off)

    const int E = in_sizes[8] / 2;            // edge_index is [2,E]
    const int N = out_size;
    float* out = (float*)d_out;

    const int DSMEM = 16 * BPQ * 16;          // 33280 B
    cudaFuncSetAttribute(edge_kernel,
                         cudaFuncAttributeMaxDynamicSharedMemorySize, DSMEM);

    int nb = (N + 255) / 256;
    zero_kernel<<<nb, 256>>>(N);
    dummy_kernel<<<1, 32>>>();   // pad launch slots: edge_kernel stays launch #4
    dummy_kernel<<<1, 32>>>();
    edge_kernel<<<296, 256, DSMEM>>>(v, rij, W0, b0, W1, b1, W2, b2,
                                     ei, ei + E, E);
    finalize_kernel<<<nb, 256>>>(out, N);
}

// round 16
// speedup vs baseline: 2.8194x; 1.0492x over previous
#include <cuda_runtime.h>
#include <cstdint>

#define FULLMASK 0xffffffffu
#define NMAX 100000
#define BPQ 130   // uint4 pitch; 130 % 8 == 2 -> all four 8-lane phases conflict-free

static __device__ float g_sum_i[NMAX];
static __device__ float g_sum_j[NMAX];
static __device__ float g_cnt_i[NMAX];
static __device__ float g_cnt_j[NMAX];

__device__ __forceinline__ uint32_t packh2(float lo, float hi) {
    uint32_t d;   // d.lo = f16(lo), d.hi = f16(hi)
    asm("cvt.rn.f16x2.f32 %0, %1, %2;" : "=r"(d) : "f"(hi), "f"(lo));
    return d;
}
__device__ __forceinline__ uint32_t h2add(uint32_t a, uint32_t b) {
    uint32_t d; asm("add.f16x2 %0, %1, %2;" : "=r"(d) : "r"(a), "r"(b)); return d;
}
__device__ __forceinline__ uint32_t h2mul(uint32_t a, uint32_t b) {
    uint32_t d; asm("mul.f16x2 %0, %1, %2;" : "=r"(d) : "r"(a), "r"(b)); return d;
}
__device__ __forceinline__ uint32_t h2fma(uint32_t a, uint32_t b, uint32_t c) {
    uint32_t d; asm("fma.rn.f16x2 %0, %1, %2, %3;" : "=r"(d) : "r"(a), "r"(b), "r"(c)); return d;
}
// silu on both halves of an f16x2: zh=z/2; zh*tanh(zh)+zh   (1 MUFU per pair)
__device__ __forceinline__ uint32_t silu2(uint32_t z) {
    uint32_t zh = h2mul(z, 0x38003800u);   // (0.5, 0.5)
    uint32_t t;
    asm("tanh.approx.f16x2 %0, %1;" : "=r"(t) : "r"(zh));
    return h2fma(zh, t, zh);
}
__device__ __forceinline__ float silu_t(float z) {
    float zh = 0.5f * z, t;
    asm("tanh.approx.f32 %0, %1;" : "=f"(t) : "f"(zh));
    return fmaf(zh, t, zh);
}
__device__ __forceinline__ void mma_f16(float* d, const uint32_t* a,
                                        uint32_t b0, uint32_t b1) {
    asm volatile(
        "mma.sync.aligned.m16n8k16.row.col.f32.f16.f16.f32 "
        "{%0,%1,%2,%3}, {%4,%5,%6,%7}, {%8,%9}, {%0,%1,%2,%3};"
        : "+f"(d[0]), "+f"(d[1]), "+f"(d[2]), "+f"(d[3])
        : "r"(a[0]), "r"(a[1]), "r"(a[2]), "r"(a[3]), "r"(b0), "r"(b1));
}

__global__ void zero_kernel(int n) {
    int t = blockIdx.x * blockDim.x + threadIdx.x;
    if (t < n) {
        g_sum_i[t] = 0.f; g_sum_j[t] = 0.f;
        g_cnt_i[t] = 0.f; g_cnt_j[t] = 0.f;
    }
}
__global__ void dummy_kernel() {}   // launch-slot padding so ncu (#4) hits edge_kernel
__global__ void finalize_kernel(float* __restrict__ out, int n) {
    int t = blockIdx.x * blockDim.x + threadIdx.x;
    if (t < n) {
        out[t] = g_sum_i[t] / fmaxf(g_cnt_i[t], 1.f)
               + g_sum_j[t] / fmaxf(g_cnt_j[t], 1.f);
    }
}

// Warp-task: 16 edges = TWO m16 tiles (rows q = dir i, q+8 = dir j).
// A-frags full k resident; n swept in 8 chunks of 16 cols. Epilogue
// (silu + W2-dot) executed as a second MMA per chunk into persistent dacc:
// C-frag of layer1 == A-frag of epilogue MMA; B = W2 in column n=0 only.
__global__ void __launch_bounds__(256, 2)
edge_kernel(const float* __restrict__ v,
            const float* __restrict__ r_ij,
            const float* __restrict__ W0,
            const float* __restrict__ b0,
            const float* __restrict__ W1,
            const float* __restrict__ b1,
            const float* __restrict__ W2,
            const float* __restrict__ b2,
            const int* __restrict__ ei0,
            const int* __restrict__ ei1,
            int E) {
    extern __shared__ uint4 Bq[];            // [16][BPQ]
    __shared__ float4 W0s4[128];
    __shared__ float2 s_b02[64];             // b0 pairs
    __shared__ uint32_t s_b1h[64];           // h2(b1 pairs): [4u+m]
    __shared__ uint2  s_w2b[32];             // W2 epilogue B-frags: [4nc+m]

    const int tid = threadIdx.x;

    // Bq[(k32*4+mm)*BPQ + n] = { h2(k0,k0+1), h2(k0+8,k0+9),
    //                            h2(k0+16,k0+17), h2(k0+24,k0+25) }, k0=32*k32+2*mm
    for (int idx = tid; idx < 16 * 128; idx += 256) {
        int rb = idx >> 7, n = idx & 127;
        int k0 = ((rb >> 2) << 5) + ((rb & 3) << 1);
        const float* wn = W1 + n * 128;
        Bq[rb * BPQ + n] = make_uint4(
            packh2(wn[k0],      wn[k0 + 1]),
            packh2(wn[k0 + 8],  wn[k0 + 9]),
            packh2(wn[k0 + 16], wn[k0 + 17]),
            packh2(wn[k0 + 24], wn[k0 + 25]));
    }
    if (tid < 128) W0s4[tid] = ((const float4*)W0)[tid];
    if (tid < 64) {
        s_b02[tid] = make_float2(b0[2 * tid], b0[2 * tid + 1]);
        int u = tid >> 2, mm = tid & 3;
        s_b1h[tid] = packh2(b1[8 * u + 2 * mm], b1[8 * u + 2 * mm + 1]);
    }
    if (tid < 32) {
        int nc = tid >> 2, mm = tid & 3;
        s_w2b[tid] = make_uint2(
            packh2(W2[16 * nc + 2 * mm],     W2[16 * nc + 2 * mm + 1]),
            packh2(W2[16 * nc + 2 * mm + 8], W2[16 * nc + 2 * mm + 9]));
    }
    __syncthreads();

    const int lane = tid & 31;
    const int m    = lane & 3;    // frag k/col group
    const int q    = lane >> 2;   // frag row group
    const float b2v = b2[0];

    const int gw = (blockIdx.x << 3) + (tid >> 5);
    const int nw = gridDim.x << 3;
    const int ntask = (E + 15) >> 4;

    for (int task = gw; task < ntask; task += nw) {
        const int base = task << 4;

        // lanes 0-15 gather 16 edges + fused count scatter
        int ii = 0, jj = 0;
        float rr = 0.f, dx = 0.f, dy = 0.f, dz = 0.f;
        if (lane < 16) {
            int e = base + lane;
            bool valid = e < E;
            int ec = valid ? e : E - 1;
            ii = ei0[ec]; jj = ei1[ec];
            float a0 = r_ij[3 * ec], a1 = r_ij[3 * ec + 1], a2 = r_ij[3 * ec + 2];
            rr = sqrtf(a0 * a0 + a1 * a1 + a2 * a2) * (1.0f / 3.0f);   // /H, H=3
            dx = v[3 * ii]     - v[3 * jj];
            dy = v[3 * ii + 1] - v[3 * jj + 1];
            dz = v[3 * ii + 2] - v[3 * jj + 2];
            if (valid) {
                atomicAdd(&g_cnt_i[ii], 1.f);
                atomicAdd(&g_cnt_j[jj], 1.f);
            }
        }
        // broadcasts: tile 0 -> edge q, tile 1 -> edge q+8
        float rrb[2], vxb[2], vyb[2], vzb[2];
        int iib[2], jjb[2];
#pragma unroll
        for (int s = 0; s < 2; s++) {
            int src = q + 8 * s;
            rrb[s] = __shfl_sync(FULLMASK, rr, src);
            vxb[s] = __shfl_sync(FULLMASK, dx, src);
            vyb[s] = __shfl_sync(FULLMASK, dy, src);
            vzb[s] = __shfl_sync(FULLMASK, dz, src);
            iib[s] = __shfl_sync(FULLMASK, ii, src);
            jjb[s] = __shfl_sync(FULLMASK, jj, src);
        }

        // ---- layer 0 ONCE: A-frags for both tiles, full k (64 regs) ----
        uint32_t af[4][2][2][4];   // [k32][p][tile][frag]
#pragma unroll
        for (int k32 = 0; k32 < 4; k32++) {
#pragma unroll
            for (int p = 0; p < 2; p++) {
#pragma unroll
                for (int cp = 0; cp < 2; cp++) {
                    int c = 32 * k32 + 16 * p + 2 * m + 8 * cp;
                    float4 wA = W0s4[c];
                    float4 wB = W0s4[c + 1];
                    float2 bb = s_b02[c >> 1];
#pragma unroll
                    for (int s = 0; s < 2; s++) {
                        float trA = fmaf(wA.x, rrb[s], bb.x);
                        float tvA = fmaf(wA.y, vxb[s], fmaf(wA.z, vyb[s], wA.w * vzb[s]));
                        float trB = fmaf(wB.x, rrb[s], bb.y);
                        float tvB = fmaf(wB.y, vxb[s], fmaf(wB.z, vyb[s], wB.w * vzb[s]));
                        af[k32][p][s][2 * cp] =
                            silu2(packh2(trA + tvA, trB + tvB));
                        af[k32][p][s][2 * cp + 1] =
                            silu2(packh2(trA - tvA, trB - tvB));
                    }
                }
            }
        }

        // ---- n sweep: 8 chunks x 16 cols; epilogue folded via MMA ----
        float dacc[2][4];
        dacc[0][0] = dacc[0][1] = dacc[0][2] = dacc[0][3] = 0.f;
        dacc[1][0] = dacc[1][1] = dacc[1][2] = dacc[1][3] = 0.f;

#pragma unroll
        for (int nc = 0; nc < 8; nc++) {
            float acc[2][2][4];   // [tile][u-within-chunk][frag]
#pragma unroll
            for (int t = 0; t < 2; t++)
#pragma unroll
                for (int u = 0; u < 2; u++)
                    acc[t][u][0] = acc[t][u][1] = acc[t][u][2] = acc[t][u][3] = 0.f;

#pragma unroll
            for (int k32 = 0; k32 < 4; k32++) {
                const uint4* bp = Bq + ((k32 << 2) + m) * BPQ + q;
                uint4 bqa = bp[16 * nc];
                uint4 bqb = bp[16 * nc + 8];
#pragma unroll
                for (int p = 0; p < 2; p++) {
                    uint32_t a0x = p ? bqa.z : bqa.x, a0y = p ? bqa.w : bqa.y;
                    uint32_t b0x = p ? bqb.z : bqb.x, b0y = p ? bqb.w : bqb.y;
                    mma_f16(acc[0][0], af[k32][p][0], a0x, a0y);
                    mma_f16(acc[1][0], af[k32][p][1], a0x, a0y);
                    mma_f16(acc[0][1], af[k32][p][0], b0x, b0y);
                    mma_f16(acc[1][1], af[k32][p][1], b0x, b0y);
                }
            }
            // epilogue MMA: A = silu(acc + b1), B = W2 (col n=0 only)
            uint2 wb = s_w2b[4 * nc + m];
            if (q != 0) { wb.x = 0u; wb.y = 0u; }
            uint32_t b1a = s_b1h[8 * nc + m];
            uint32_t b1b = s_b1h[8 * nc + 4 + m];
#pragma unroll
            for (int t = 0; t < 2; t++) {
                uint32_t eaf[4];
                eaf[0] = silu2(h2add(packh2(acc[t][0][0], acc[t][0][1]), b1a));
                eaf[1] = silu2(h2add(packh2(acc[t][0][2], acc[t][0][3]), b1a));
                eaf[2] = silu2(h2add(packh2(acc[t][1][0], acc[t][1][1]), b1b));
                eaf[3] = silu2(h2add(packh2(acc[t][1][2], acc[t][1][3]), b1b));
                mma_f16(dacc[t], eaf, wb.x, wb.y);
            }
        }

        // ---- scatter: dacc col 0 holds the k-summed dot (lanes m==0) ----
        if (m == 0) {
#pragma unroll
            for (int t = 0; t < 2; t++) {
                if (base + q + 8 * t < E) {
                    atomicAdd(&g_sum_i[iib[t]], dacc[t][0] + b2v);
                    atomicAdd(&g_sum_j[jjb[t]], dacc[t][2] + b2v);
                }
            }
        }
    }
}

extern "C" void kernel_launch(void* const* d_in, const int* in_sizes, int n_in,
                              void* d_out, int out_size) {
    const float* v   = (const float*)d_in[0];
    const float* rij = (const float*)d_in[1];
    const float* W0  = (const float*)d_in[2];
    const float* b0  = (const float*)d_in[3];
    const float* W1  = (const float*)d_in[4];
    const float* b1  = (const float*)d_in[5];
    const float* W2  = (const float*)d_in[6];
    const float* b2  = (const float*)d_in[7];
    const int*   ei  = (const int*)d_in[8];   // int32 on device (JAX x64 off)

    const int E = in_sizes[8] / 2;            // edge_index is [2,E]
    const int N = out_size;
    float* out = (float*)d_out;

    const int DSMEM = 16 * BPQ * 16;          // 33280 B
    cudaFuncSetAttribute(edge_kernel,
                         cudaFuncAttributeMaxDynamicSharedMemorySize, DSMEM);

    int nb = (N + 255) / 256;
    zero_kernel<<<nb, 256>>>(N);
    dummy_kernel<<<1, 32>>>();   // pad launch slots: edge_kernel stays launch #4
    dummy_kernel<<<1, 32>>>();
    edge_kernel<<<296, 256, DSMEM>>>(v, rij, W0, b0, W1, b1, W2, b2,
                                     ei, ei + E, E);
    finalize_kernel<<<nb, 256>>>(out, N);
}

// round 17
// speedup vs baseline: 2.9034x; 1.0298x over previous
#include <cuda_runtime.h>
#include <cstdint>

#define FULLMASK 0xffffffffu
#define NMAX 100000
#define BPQ 130   // uint4 pitch; 130 % 8 == 2 -> all four 8-lane phases conflict-free

static __device__ float g_sum_i[NMAX];
static __device__ float g_sum_j[NMAX];
static __device__ float g_cnt_i[NMAX];
static __device__ float g_cnt_j[NMAX];

__device__ __forceinline__ uint32_t packh2(float lo, float hi) {
    uint32_t d;   // d.lo = f16(lo), d.hi = f16(hi)
    asm("cvt.rn.f16x2.f32 %0, %1, %2;" : "=r"(d) : "f"(hi), "f"(lo));
    return d;
}
__device__ __forceinline__ uint32_t to_tf32(float f) {
    uint32_t r;
    asm("cvt.rna.tf32.f32 %0, %1;" : "=r"(r) : "f"(f));
    return r;
}
__device__ __forceinline__ uint32_t h2mul(uint32_t a, uint32_t b) {
    uint32_t d; asm("mul.f16x2 %0, %1, %2;" : "=r"(d) : "r"(a), "r"(b)); return d;
}
__device__ __forceinline__ uint32_t h2fma(uint32_t a, uint32_t b, uint32_t c) {
    uint32_t d; asm("fma.rn.f16x2 %0, %1, %2, %3;" : "=r"(d) : "r"(a), "r"(b), "r"(c)); return d;
}
// silu on both halves of an f16x2: zh=z/2; zh*tanh(zh)+zh   (1 MUFU per pair)
__device__ __forceinline__ uint32_t silu2(uint32_t z) {
    uint32_t zh = h2mul(z, 0x38003800u);   // (0.5, 0.5)
    uint32_t t;
    asm("tanh.approx.f16x2 %0, %1;" : "=r"(t) : "r"(zh));
    return h2fma(zh, t, zh);
}
__device__ __forceinline__ void mma_f16(float* d, const uint32_t* a,
                                        uint32_t b0, uint32_t b1) {
    asm volatile(
        "mma.sync.aligned.m16n8k16.row.col.f32.f16.f16.f32 "
        "{%0,%1,%2,%3}, {%4,%5,%6,%7}, {%8,%9}, {%0,%1,%2,%3};"
        : "+f"(d[0]), "+f"(d[1]), "+f"(d[2]), "+f"(d[3])
        : "r"(a[0]), "r"(a[1]), "r"(a[2]), "r"(a[3]), "r"(b0), "r"(b1));
}
// layer-0 MMA: 16x8x4 tf32; bias pre-loaded in the accumulator
__device__ __forceinline__ void mma_tf32k4(float* d, uint32_t a0, uint32_t a1,
                                           uint32_t b0) {
    asm volatile(
        "mma.sync.aligned.m16n8k4.row.col.f32.tf32.tf32.f32 "
        "{%0,%1,%2,%3}, {%4,%5}, {%6}, {%0,%1,%2,%3};"
        : "+f"(d[0]), "+f"(d[1]), "+f"(d[2]), "+f"(d[3])
        : "r"(a0), "r"(a1), "r"(b0));
}

__global__ void zero_kernel(int n) {
    int t = blockIdx.x * blockDim.x + threadIdx.x;
    if (t < n) {
        g_sum_i[t] = 0.f; g_sum_j[t] = 0.f;
        g_cnt_i[t] = 0.f; g_cnt_j[t] = 0.f;
    }
}
__global__ void dummy_kernel() {}   // launch-slot padding so ncu (#4) hits edge_kernel
__global__ void finalize_kernel(float* __restrict__ out, int n) {
    int t = blockIdx.x * blockDim.x + threadIdx.x;
    if (t < n) {
        out[t] = g_sum_i[t] / fmaxf(g_cnt_i[t], 1.f)
               + g_sum_j[t] / fmaxf(g_cnt_j[t], 1.f);
    }
}

// Warp-task: 16 edges = TWO m16 tiles (rows q = dir i, q+8 = dir j).
// ALL three layers on tensor cores:
//   layer0: m16n8k4 tf32, X a-frag built inline, b0 in accumulator init
//   layer1: m16n8k16 f16, acc init = b1
//   layer2: m16n8k16 f16 with B = W2 in column 0 (k-sum in the MMA)
__global__ void __launch_bounds__(256, 2)
edge_kernel(const float* __restrict__ v,
            const float* __restrict__ r_ij,
            const float* __restrict__ W0,
            const float* __restrict__ b0,
            const float* __restrict__ W1,
            const float* __restrict__ b1,
            const float* __restrict__ W2,
            const float* __restrict__ b2,
            const int* __restrict__ ei0,
            const int* __restrict__ ei1,
            int E) {
    extern __shared__ uint4 Bq[];            // [16][BPQ]
    __shared__ uint32_t s_w0t[512];          // tf32 W0 b-frags: [nc8*32 + lane]
    __shared__ float2 s_b02[64];             // b0 pairs (natural order)
    __shared__ float2 s_b12[64];             // b1 pairs (natural order)
    __shared__ uint2  s_w2b[32];             // W2 epilogue B-frags: [4nc+m]

    const int tid = threadIdx.x;

    // Bq[(k32*4+mm)*BPQ + n] = { h2(k0,k0+1), h2(k0+8,k0+9),
    //                            h2(k0+16,k0+17), h2(k0+24,k0+25) }, k0=32*k32+2*mm
    for (int idx = tid; idx < 16 * 128; idx += 256) {
        int rb = idx >> 7, n = idx & 127;
        int k0 = ((rb >> 2) << 5) + ((rb & 3) << 1);
        const float* wn = W1 + n * 128;
        Bq[rb * BPQ + n] = make_uint4(
            packh2(wn[k0],      wn[k0 + 1]),
            packh2(wn[k0 + 8],  wn[k0 + 9]),
            packh2(wn[k0 + 16], wn[k0 + 17]),
            packh2(wn[k0 + 24], wn[k0 + 25]));
    }
    // W0 b-frag: lane (mm=l&3, qq=l>>2) of chunk nc8 holds tf32(W0[8nc8+qq][mm])
    for (int idx = tid; idx < 512; idx += 256) {
        int nc8 = idx >> 5, l = idx & 31;
        s_w0t[idx] = to_tf32(W0[(8 * nc8 + (l >> 2)) * 4 + (l & 3)]);
    }
    if (tid < 64) {
        s_b02[tid] = make_float2(b0[2 * tid], b0[2 * tid + 1]);
        s_b12[tid] = make_float2(b1[2 * tid], b1[2 * tid + 1]);
    }
    if (tid < 32) {
        int nc = tid >> 2, mm = tid & 3;
        s_w2b[tid] = make_uint2(
            packh2(W2[16 * nc + 2 * mm],     W2[16 * nc + 2 * mm + 1]),
            packh2(W2[16 * nc + 2 * mm + 8], W2[16 * nc + 2 * mm + 9]));
    }
    __syncthreads();

    const int lane = tid & 31;
    const int m    = lane & 3;    // frag k/col group
    const int q    = lane >> 2;   // frag row group
    const float b2v = b2[0];

    const int gw = (blockIdx.x << 3) + (tid >> 5);
    const int nw = gridDim.x << 3;
    const int ntask = (E + 15) >> 4;

    for (int task = gw; task < ntask; task += nw) {
        const int base = task << 4;

        // lanes 0-15 gather 16 edges + fused count scatter
        int ii = 0, jj = 0;
        float rr = 0.f, dx = 0.f, dy = 0.f, dz = 0.f;
        if (lane < 16) {
            int e = base + lane;
            bool valid = e < E;
            int ec = valid ? e : E - 1;
            ii = ei0[ec]; jj = ei1[ec];
            float a0 = r_ij[3 * ec], a1 = r_ij[3 * ec + 1], a2 = r_ij[3 * ec + 2];
            rr = sqrtf(a0 * a0 + a1 * a1 + a2 * a2) * (1.0f / 3.0f);   // /H, H=3
            dx = v[3 * ii]     - v[3 * jj];
            dy = v[3 * ii + 1] - v[3 * jj + 1];
            dz = v[3 * ii + 2] - v[3 * jj + 2];
            if (valid) {
                atomicAdd(&g_cnt_i[ii], 1.f);
                atomicAdd(&g_cnt_j[jj], 1.f);
            }
        }
        // broadcasts: tile 0 -> edge q, tile 1 -> edge q+8
        float rrb[2], vxb[2], vyb[2], vzb[2];
        int iib[2], jjb[2];
#pragma unroll
        for (int s = 0; s < 2; s++) {
            int src = q + 8 * s;
            rrb[s] = __shfl_sync(FULLMASK, rr, src);
            vxb[s] = __shfl_sync(FULLMASK, dx, src);
            vyb[s] = __shfl_sync(FULLMASK, dy, src);
            vzb[s] = __shfl_sync(FULLMASK, dz, src);
            iib[s] = __shfl_sync(FULLMASK, ii, src);
            jjb[s] = __shfl_sync(FULLMASK, jj, src);
        }

        // ---- layer 0 via tf32 m16n8k4 MMA ----
        // A row q (dir i): x = {rr,vx,vy,vz}[m]; row q+8 (dir j): v negated
        uint32_t xa[2][2];
#pragma unroll
        for (int s = 0; s < 2; s++) {
            float a0v = (m == 0) ? rrb[s] : (m == 1) ? vxb[s]
                      : (m == 2) ? vyb[s] : vzb[s];
            float a1v = (m == 0) ? rrb[s] : (m == 1) ? -vxb[s]
                      : (m == 2) ? -vyb[s] : -vzb[s];
            xa[s][0] = to_tf32(a0v);
            xa[s][1] = to_tf32(a1v);
        }

        uint32_t af[4][2][2][4];   // [k32][p][tile][frag]
#pragma unroll
        for (int nc8 = 0; nc8 < 16; nc8++) {
            const int k32 = nc8 >> 2, p = (nc8 >> 1) & 1, cp = nc8 & 1;
            uint32_t bw = s_w0t[(nc8 << 5) + lane];
            float2 bb = s_b02[(nc8 << 2) + m];
#pragma unroll
            for (int s = 0; s < 2; s++) {
                float c[4] = {bb.x, bb.y, bb.x, bb.y};
                mma_tf32k4(c, xa[s][0], xa[s][1], bw);
                af[k32][p][s][2 * cp]     = silu2(packh2(c[0], c[1]));
                af[k32][p][s][2 * cp + 1] = silu2(packh2(c[2], c[3]));
            }
        }

        // ---- n sweep: 8 chunks x 16 cols; layer-1 acc init = b1;
        //      epilogue folded via W2 MMA into persistent dacc ----
        float dacc[2][4];
        dacc[0][0] = dacc[0][1] = dacc[0][2] = dacc[0][3] = 0.f;
        dacc[1][0] = dacc[1][1] = dacc[1][2] = dacc[1][3] = 0.f;

#pragma unroll
        for (int nc = 0; nc < 8; nc++) {
            float2 bza = s_b12[8 * nc + m];
            float2 bzb = s_b12[8 * nc + 4 + m];
            float acc[2][2][4];   // [tile][u][frag]
#pragma unroll
            for (int t = 0; t < 2; t++) {
                acc[t][0][0] = bza.x; acc[t][0][1] = bza.y;
                acc[t][0][2] = bza.x; acc[t][0][3] = bza.y;
                acc[t][1][0] = bzb.x; acc[t][1][1] = bzb.y;
                acc[t][1][2] = bzb.x; acc[t][1][3] = bzb.y;
            }

#pragma unroll
            for (int k32 = 0; k32 < 4; k32++) {
                const uint4* bp = Bq + ((k32 << 2) + m) * BPQ + q;
                uint4 bqa = bp[16 * nc];
                uint4 bqb = bp[16 * nc + 8];
#pragma unroll
                for (int p = 0; p < 2; p++) {
                    uint32_t a0x = p ? bqa.z : bqa.x, a0y = p ? bqa.w : bqa.y;
                    uint32_t b0x = p ? bqb.z : bqb.x, b0y = p ? bqb.w : bqb.y;
                    mma_f16(acc[0][0], af[k32][p][0], a0x, a0y);
                    mma_f16(acc[1][0], af[k32][p][1], a0x, a0y);
                    mma_f16(acc[0][1], af[k32][p][0], b0x, b0y);
                    mma_f16(acc[1][1], af[k32][p][1], b0x, b0y);
                }
            }
            // epilogue MMA: A = silu(acc) (bias already inside), B = W2 col 0
            uint2 wb = s_w2b[4 * nc + m];
            if (q != 0) { wb.x = 0u; wb.y = 0u; }
#pragma unroll
            for (int t = 0; t < 2; t++) {
                uint32_t eaf[4];
                eaf[0] = silu2(packh2(acc[t][0][0], acc[t][0][1]));
                eaf[1] = silu2(packh2(acc[t][0][2], acc[t][0][3]));
                eaf[2] = silu2(packh2(acc[t][1][0], acc[t][1][1]));
                eaf[3] = silu2(packh2(acc[t][1][2], acc[t][1][3]));
                mma_f16(dacc[t], eaf, wb.x, wb.y);
            }
        }

        // ---- scatter: dacc col 0 holds the k-summed dot (lanes m==0) ----
        if (m == 0) {
#pragma unroll
            for (int t = 0; t < 2; t++) {
                if (base + q + 8 * t < E) {
                    atomicAdd(&g_sum_i[iib[t]], dacc[t][0] + b2v);
                    atomicAdd(&g_sum_j[jjb[t]], dacc[t][2] + b2v);
                }
            }
        }
    }
}

extern "C" void kernel_launch(void* const* d_in, const int* in_sizes, int n_in,
                              void* d_out, int out_size) {
    const float* v   = (const float*)d_in[0];
    const float* rij = (const float*)d_in[1];
    const float* W0  = (const float*)d_in[2];
    const float* b0  = (const float*)d_in[3];
    const float* W1  = (const float*)d_in[4];
    const float* b1  = (const float*)d_in[5];
    const float* W2  = (const float*)d_in[6];
    const float* b2  = (const float*)d_in[7];
    const int*   ei  = (const int*)d_in[8];   // int32 on device (JAX x64 off)

    const int E = in_sizes[8] / 2;            // edge_index is [2,E]
    const int N = out_size;
    float* out = (float*)d_out;

    const int DSMEM = 16 * BPQ * 16;          // 33280 B
    cudaFuncSetAttribute(edge_kernel,
                         cudaFuncAttributeMaxDynamicSharedMemorySize, DSMEM);

    int nb = (N + 255) / 256;
    zero_kernel<<<nb, 256>>>(N);
    dummy_kernel<<<1, 32>>>();   // pad launch slots: edge_kernel stays launch #4
    dummy_kernel<<<1, 32>>>();
    edge_kernel<<<296, 256, DSMEM>>>(v, rij, W0, b0, W1, b1, W2, b2,
                                     ei, ei + E, E);
    finalize_kernel<<<nb, 256>>>(out, N);
}